// round 1
// baseline (speedup 1.0000x reference)
#include <cuda_runtime.h>

// Problem: B=8, C=256, H=W=64, O=256, K=3, E=3
// out[b,o,y,x] = sum_{c,kh,kw} q[b,c,y+kh-1,x+kw-1] * w2[b,o,c,kh,kw]
// w2[b,o,c,.] = sum_e gates[b,e]*(experts[e,o,c,.] + experts[e,o,c+C,.])
// gates[b] = softmax( yctx[b] @ (gw[:C]+gw[C:]) + gb )

#define BQ 8
#define CQ 256
#define HQ 64
#define WQ 64
#define OQ 256

__device__ float g_yctx[BQ * CQ];
__device__ float g_gates[BQ * 3];
__device__ float g_w2[(size_t)BQ * OQ * CQ * 9];  // [b][o][c*9+t], ~18.9 MB

// ---------------------------------------------------------------------------
// Kernel 1: global average pool of y -> g_yctx  (one block per (b,c))
// ---------------------------------------------------------------------------
__global__ void k_mean(const float* __restrict__ y) {
    int bc = blockIdx.x;                     // 0..2047
    const float* p = y + (size_t)bc * (HQ * WQ);
    float s = 0.f;
    for (int i = threadIdx.x; i < HQ * WQ; i += 256) s += p[i];
    __shared__ float sm[256];
    sm[threadIdx.x] = s;
    __syncthreads();
    for (int st = 128; st > 0; st >>= 1) {
        if (threadIdx.x < st) sm[threadIdx.x] += sm[threadIdx.x + st];
        __syncthreads();
    }
    if (threadIdx.x == 0) g_yctx[bc] = sm[0] * (1.f / (HQ * WQ));
}

// ---------------------------------------------------------------------------
// Kernel 2: gates[b] = softmax over 3 experts (one block per batch)
// ---------------------------------------------------------------------------
__global__ void k_gates(const float* __restrict__ gw, const float* __restrict__ gb) {
    int b = blockIdx.x;
    int c = threadIdx.x;                     // 0..255
    float v = g_yctx[b * CQ + c];
    float p0 = v * (gw[c * 3 + 0] + gw[(c + CQ) * 3 + 0]);
    float p1 = v * (gw[c * 3 + 1] + gw[(c + CQ) * 3 + 1]);
    float p2 = v * (gw[c * 3 + 2] + gw[(c + CQ) * 3 + 2]);
    __shared__ float sm[3][256];
    sm[0][c] = p0; sm[1][c] = p1; sm[2][c] = p2;
    __syncthreads();
    for (int st = 128; st > 0; st >>= 1) {
        if (c < st) {
            sm[0][c] += sm[0][c + st];
            sm[1][c] += sm[1][c + st];
            sm[2][c] += sm[2][c + st];
        }
        __syncthreads();
    }
    if (c == 0) {
        float l0 = sm[0][0] + gb[0], l1 = sm[1][0] + gb[1], l2 = sm[2][0] + gb[2];
        float m = fmaxf(l0, fmaxf(l1, l2));
        float e0 = expf(l0 - m), e1 = expf(l1 - m), e2 = expf(l2 - m);
        float inv = 1.f / (e0 + e1 + e2);
        g_gates[b * 3 + 0] = e0 * inv;
        g_gates[b * 3 + 1] = e1 * inv;
        g_gates[b * 3 + 2] = e2 * inv;
    }
}

// ---------------------------------------------------------------------------
// Kernel 3: fold experts -> per-batch weights (also folds 2C -> C)
// experts: [E, O, 2C, 3, 3]; w2: [b][o][c*9+t]
// ---------------------------------------------------------------------------
__global__ void k_fold(const float* __restrict__ experts) {
    int idx = blockIdx.x * 256 + threadIdx.x;        // 0 .. O*C*9-1
    if (idx >= OQ * CQ * 9) return;
    int o   = idx / (CQ * 9);
    int rem = idx % (CQ * 9);                        // c*9 + t
    const size_t ES = (size_t)OQ * (2 * CQ) * 9;     // per-expert stride
    size_t base = (size_t)o * (2 * CQ * 9) + rem;
    float f0 = experts[base]            + experts[base + CQ * 9];
    float f1 = experts[ES + base]       + experts[ES + base + CQ * 9];
    float f2 = experts[2 * ES + base]   + experts[2 * ES + base + CQ * 9];
    #pragma unroll
    for (int b = 0; b < BQ; b++) {
        float g0 = g_gates[b * 3 + 0];
        float g1 = g_gates[b * 3 + 1];
        float g2 = g_gates[b * 3 + 2];
        g_w2[(size_t)b * (OQ * CQ * 9) + idx] = g0 * f0 + g1 * f1 + g2 * f2;
    }
}

// ---------------------------------------------------------------------------
// Kernel 4: direct conv, per-batch weights.
// Block = 64 output channels x (8 rows x 16 cols) pixel tile. 256 threads.
// Thread = 8 o x 4 px (consecutive cols). C processed in chunks of 4.
// ---------------------------------------------------------------------------
__global__ __launch_bounds__(256, 2)
void k_conv(const float* __restrict__ q, float* __restrict__ out) {
    __shared__ float xs[4][10][19];    // [ci][row(-1..8)][col(-1..16)], pad 19
    __shared__ float ws[4][9][64];     // [ci][tap][o]

    int b    = blockIdx.z >> 2;
    int o0   = (blockIdx.z & 3) * 64;
    int row0 = blockIdx.y * 8;
    int col0 = blockIdx.x * 16;
    int tid  = threadIdx.x;

    int pxq   = tid & 31;              // 32 pixel groups
    int opart = tid >> 5;              // 8 o-groups (uniform within warp)
    int prow  = pxq >> 2;              // 0..7
    int pcolb = (pxq & 3) << 2;        // 0,4,8,12

    float acc[8][4];
    #pragma unroll
    for (int i = 0; i < 8; i++)
        #pragma unroll
        for (int j = 0; j < 4; j++) acc[i][j] = 0.f;

    const float* qb = q    + (size_t)b * CQ * HQ * WQ;
    const float* wb = g_w2 + (size_t)b * OQ * CQ * 9 + (size_t)o0 * CQ * 9;
    int woi = tid >> 2, wci = tid & 3; // weight-loader mapping: 64 o x 4 c

    for (int c0 = 0; c0 < CQ; c0 += 4) {
        // ---- load input patch (with halo + zero pad) ----
        for (int i = tid; i < 4 * 10 * 18; i += 256) {
            int ci = i / 180;
            int r  = (i / 18) % 10;
            int cc = i % 18;
            int gy = row0 - 1 + r;
            int gx = col0 - 1 + cc;
            float v = 0.f;
            if ((unsigned)gy < (unsigned)HQ && (unsigned)gx < (unsigned)WQ)
                v = qb[((size_t)(c0 + ci) * HQ + gy) * WQ + gx];
            xs[ci][r][cc] = v;
        }
        // ---- load weights: each thread 9 consecutive taps of (woi, wci) ----
        {
            const float* wp = wb + (size_t)woi * (CQ * 9) + (size_t)(c0 + wci) * 9;
            #pragma unroll
            for (int t = 0; t < 9; t++) ws[wci][t][woi] = wp[t];
        }
        __syncthreads();

        #pragma unroll
        for (int ci = 0; ci < 4; ci++) {
            float xr[3][6];
            #pragma unroll
            for (int kr = 0; kr < 3; kr++)
                #pragma unroll
                for (int cc = 0; cc < 6; cc++)
                    xr[kr][cc] = xs[ci][prow + kr][pcolb + cc];

            #pragma unroll
            for (int t = 0; t < 9; t++) {
                int kr = t / 3, kc = t % 3;
                float wv[8];
                #pragma unroll
                for (int oi = 0; oi < 8; oi++)       // warp-uniform address: broadcast
                    wv[oi] = ws[ci][t][opart * 8 + oi];
                #pragma unroll
                for (int oi = 0; oi < 8; oi++)
                    #pragma unroll
                    for (int j = 0; j < 4; j++)
                        acc[oi][j] = fmaf(wv[oi], xr[kr][kc + j], acc[oi][j]);
            }
        }
        __syncthreads();
    }

    // ---- epilogue: float4 stores ----
    int orow = row0 + prow;
    #pragma unroll
    for (int oi = 0; oi < 8; oi++) {
        int o = o0 + opart * 8 + oi;
        float4 v = make_float4(acc[oi][0], acc[oi][1], acc[oi][2], acc[oi][3]);
        *(float4*)(out + (((size_t)b * OQ + o) * HQ + orow) * WQ + col0 + pcolb) = v;
    }
}

// ---------------------------------------------------------------------------
extern "C" void kernel_launch(void* const* d_in, const int* in_sizes, int n_in,
                              void* d_out, int out_size) {
    const float* q       = (const float*)d_in[0];
    const float* y       = (const float*)d_in[1];
    const float* experts = (const float*)d_in[2];
    const float* gate_w  = (const float*)d_in[3];
    const float* gate_b  = (const float*)d_in[4];
    float* out = (float*)d_out;

    k_mean<<<BQ * CQ, 256>>>(y);
    k_gates<<<BQ, 256>>>(gate_w, gate_b);
    k_fold<<<(OQ * CQ * 9 + 255) / 256, 256>>>(experts);

    dim3 grid(WQ / 16, HQ / 8, BQ * (OQ / 64));   // (4, 8, 32)
    k_conv<<<grid, 256>>>(q, out);
}

// round 3
// speedup vs baseline: 4.5379x; 4.5379x over previous
#include <cuda_runtime.h>
#include <cuda_fp16.h>
#include <cstdint>

// Problem: B=8, C=256, H=W=64, O=256, K=3, E=3
// out[b,o,y,x] = sum_{c,t} w2[b,o,t,c] * q[b,c,y+kr-1,x+kc-1]
// w2[b,o,t,c] = fp16( sum_e gates[b,e]*(experts[e,o,c,t]+experts[e,o,c+C,t]) )
// Conv as fp16 mma.sync implicit GEMM (HMMA fallback; tcgen05 not available
// on compute_103 virtual arch). M=256(o) x N=4096(px) x K=2304 per batch.

#define BQ 8
#define CQ 256
#define HQ 64
#define WQ 64
#define OQ 256

__device__ float  g_yctx[BQ * CQ];
__device__ float  g_gates[BQ * 3];
__device__ __half g_w2[(size_t)BQ * OQ * 2304];   // [b][o][t*256+c]

__device__ __forceinline__ uint32_t smem_u32(const void* p) {
    uint32_t a;
    asm("{ .reg .u64 t; cvta.to.shared.u64 t, %1; cvt.u32.u64 %0, t; }" : "=r"(a) : "l"(p));
    return a;
}

// ---------------------------------------------------------------------------
// Kernel 1: global average pool of y -> g_yctx
// ---------------------------------------------------------------------------
__global__ void k_mean(const float* __restrict__ y) {
    int bc = blockIdx.x;
    const float* p = y + (size_t)bc * (HQ * WQ);
    float s = 0.f;
    for (int i = threadIdx.x; i < HQ * WQ; i += 256) s += p[i];
    __shared__ float sm[256];
    sm[threadIdx.x] = s;
    __syncthreads();
    for (int st = 128; st > 0; st >>= 1) {
        if (threadIdx.x < st) sm[threadIdx.x] += sm[threadIdx.x + st];
        __syncthreads();
    }
    if (threadIdx.x == 0) g_yctx[bc] = sm[0] * (1.f / (HQ * WQ));
}

// ---------------------------------------------------------------------------
// Kernel 2: softmax gates
// ---------------------------------------------------------------------------
__global__ void k_gates(const float* __restrict__ gw, const float* __restrict__ gb) {
    int b = blockIdx.x;
    int c = threadIdx.x;
    float v = g_yctx[b * CQ + c];
    float p0 = v * (gw[c * 3 + 0] + gw[(c + CQ) * 3 + 0]);
    float p1 = v * (gw[c * 3 + 1] + gw[(c + CQ) * 3 + 1]);
    float p2 = v * (gw[c * 3 + 2] + gw[(c + CQ) * 3 + 2]);
    __shared__ float sm[3][256];
    sm[0][c] = p0; sm[1][c] = p1; sm[2][c] = p2;
    __syncthreads();
    for (int st = 128; st > 0; st >>= 1) {
        if (c < st) {
            sm[0][c] += sm[0][c + st];
            sm[1][c] += sm[1][c + st];
            sm[2][c] += sm[2][c + st];
        }
        __syncthreads();
    }
    if (c == 0) {
        float l0 = sm[0][0] + gb[0], l1 = sm[1][0] + gb[1], l2 = sm[2][0] + gb[2];
        float m = fmaxf(l0, fmaxf(l1, l2));
        float e0 = expf(l0 - m), e1 = expf(l1 - m), e2 = expf(l2 - m);
        float inv = 1.f / (e0 + e1 + e2);
        g_gates[b * 3 + 0] = e0 * inv;
        g_gates[b * 3 + 1] = e1 * inv;
        g_gates[b * 3 + 2] = e2 * inv;
    }
}

// ---------------------------------------------------------------------------
// Kernel 3: fold experts -> per-batch tap-major fp16 weights
// block = one o (256 threads = c)
// ---------------------------------------------------------------------------
__global__ void k_fold(const float* __restrict__ experts) {
    int o = blockIdx.x;
    int c = threadIdx.x;
    const size_t ES = (size_t)OQ * (2 * CQ) * 9;
    float f[3][9];
#pragma unroll
    for (int e = 0; e < 3; e++) {
        const float* p = experts + e * ES + (size_t)o * (2 * CQ * 9) + (size_t)c * 9;
#pragma unroll
        for (int t = 0; t < 9; t++) f[e][t] = p[t] + p[CQ * 9 + t];
    }
#pragma unroll
    for (int b = 0; b < BQ; b++) {
        float g0 = g_gates[b * 3 + 0];
        float g1 = g_gates[b * 3 + 1];
        float g2 = g_gates[b * 3 + 2];
        __half* wdst = g_w2 + ((size_t)b * OQ + o) * 2304;
#pragma unroll
        for (int t = 0; t < 9; t++)
            wdst[t * 256 + c] = __float2half_rn(g0 * f[0][t] + g1 * f[1][t] + g2 * f[2][t]);
    }
}

// ---------------------------------------------------------------------------
// Kernel 4: fp16 mma.sync implicit-GEMM conv.
// CTA: (b, o-half 128, 2 image rows = 128 px). 8 warps 2(M)x4(N), warp 64x32.
// K-loop: 8 chunks of 32 ch x 9 taps x 2 k16-steps.
// SMEM: staging [4 r][66 x][32 ci] fp16, 72B stride (conflict-free B LDS);
//       A [128 o][32 ci] fp16, 80B rows (conflict-free ldmatrix), dbl-buffered.
// ---------------------------------------------------------------------------
#define A_STRIDE 80
#define A_BYTES  (128 * A_STRIDE)
#define S_STRIDE 72

__global__ __launch_bounds__(256, 2)
void k_conv(const float* __restrict__ q, float* __restrict__ out) {
    __shared__ __align__(16) unsigned char As_[2][A_BYTES];        // 20480 B
    __shared__ __align__(16) unsigned char Bs_[4 * 66 * S_STRIDE]; // 19008 B

    const uint32_t asBase = smem_u32(As_);

    int tid  = threadIdx.x;
    int lane = tid & 31;
    int warp = tid >> 5;
    int wm   = warp >> 2;      // 0..1  (64 o rows)
    int wn   = warp & 3;       // 0..3  (32 px cols)

    int nt = blockIdx.x;       // 0..31 : 2 image rows each
    int o0 = blockIdx.y * 128;
    int b  = blockIdx.z;
    int y0 = nt * 2;

    const float* qb = q + (size_t)b * CQ * HQ * WQ;
    const __half* wb = g_w2 + ((size_t)b * OQ + o0) * 2304;

    float acc[4][4][4];
#pragma unroll
    for (int i = 0; i < 4; i++)
#pragma unroll
        for (int j = 0; j < 4; j++)
#pragma unroll
            for (int k = 0; k < 4; k++) acc[i][j][k] = 0.f;

    // precomputed per-thread B base pieces
    int tg = lane & 3;             // k pair selector
    int g8 = lane >> 2;            // n within frag

    for (int cc = 0; cc < 8; cc++) {
        int c0 = cc * 32;
        __syncthreads();   // staging + A-buf0 safe to overwrite

        // ---- stage q chunk (fp32 -> fp16), [r][x][ci] ----
        for (int e = tid; e < 32 * 264; e += 256) {
            int ci  = e >> 8;            // e / 264? no -- use exact div
            // exact: e = ci*264 + rem
            ci = e / 264;
            int rem = e - ci * 264;
            int r = rem / 66;
            int x = rem - r * 66;
            int gy = y0 - 1 + r;
            int gx = x - 1;
            float v = 0.f;
            if ((unsigned)gy < (unsigned)HQ && (unsigned)gx < (unsigned)WQ)
                v = qb[(size_t)(c0 + ci) * (HQ * WQ) + gy * WQ + gx];
            *(__half*)(Bs_ + (r * 66 + x) * S_STRIDE + ci * 2) = __float2half_rn(v);
        }

        for (int t = 0; t < 9; t++) {
            int buf = t & 1;
            // ---- load A tile [128][32] into As_[buf] ----
            {
                int o   = tid >> 1;
                int ci0 = (tid & 1) << 4;
                const __half* wp = wb + (size_t)o * 2304 + t * 256 + c0 + ci0;
                uint4 v0 = *(const uint4*)wp;
                uint4 v1 = *((const uint4*)wp + 1);
                unsigned char* dst = As_[buf] + o * A_STRIDE + ci0 * 2;
                *(uint4*)dst = v0;
                *(uint4*)(dst + 16) = v1;
            }
            __syncthreads();

            int kr = t / 3, kc = t - kr * 3;

#pragma unroll
            for (int k16 = 0; k16 < 2; k16++) {
                // ---- A fragments via ldmatrix x4 ----
                uint32_t a[4][4];
#pragma unroll
                for (int fm = 0; fm < 4; fm++) {
                    int row = wm * 64 + fm * 16 + (lane & 15);
                    uint32_t addr = asBase + buf * A_BYTES + row * A_STRIDE
                                  + ((lane >> 4) << 4) + (k16 << 5);
                    asm volatile(
                        "ldmatrix.sync.aligned.m8n8.x4.shared.b16 {%0,%1,%2,%3}, [%4];"
                        : "=r"(a[fm][0]), "=r"(a[fm][1]), "=r"(a[fm][2]), "=r"(a[fm][3])
                        : "r"(addr));
                }
                // ---- B fragments: direct LDS with tap shift ----
                uint32_t bf[4][2];
#pragma unroll
                for (int fn = 0; fn < 4; fn++) {
                    int n  = wn * 32 + fn * 8 + g8;
                    int py = n >> 6, px = n & 63;
                    const unsigned char* sp = Bs_ +
                        ((py + kr) * 66 + px + kc) * S_STRIDE + ((k16 << 4) + (tg << 1)) * 2;
                    bf[fn][0] = *(const uint32_t*)sp;
                    bf[fn][1] = *(const uint32_t*)(sp + 16);
                }
                // ---- 16 MMAs ----
#pragma unroll
                for (int fm = 0; fm < 4; fm++)
#pragma unroll
                    for (int fn = 0; fn < 4; fn++) {
                        asm volatile(
                            "mma.sync.aligned.m16n8k16.row.col.f32.f16.f16.f32 "
                            "{%0,%1,%2,%3}, {%4,%5,%6,%7}, {%8,%9}, {%0,%1,%2,%3};"
                            : "+f"(acc[fm][fn][0]), "+f"(acc[fm][fn][1]),
                              "+f"(acc[fm][fn][2]), "+f"(acc[fm][fn][3])
                            : "r"(a[fm][0]), "r"(a[fm][1]), "r"(a[fm][2]), "r"(a[fm][3]),
                              "r"(bf[fn][0]), "r"(bf[fn][1]));
                    }
            }
        }
    }

    // ---- epilogue ----
#pragma unroll
    for (int fm = 0; fm < 4; fm++)
#pragma unroll
        for (int fn = 0; fn < 4; fn++) {
            int o  = o0 + wm * 64 + fm * 16 + g8;
            int n  = wn * 32 + fn * 8 + tg * 2;
            int py = n >> 6, px = n & 63;
            float* dst = out + (((size_t)(b * OQ + o)) * HQ + y0 + py) * WQ + px;
            *(float2*)dst = make_float2(acc[fm][fn][0], acc[fm][fn][1]);
            *(float2*)(dst + 8 * HQ * WQ) = make_float2(acc[fm][fn][2], acc[fm][fn][3]);
        }
}

// ---------------------------------------------------------------------------
extern "C" void kernel_launch(void* const* d_in, const int* in_sizes, int n_in,
                              void* d_out, int out_size) {
    const float* q       = (const float*)d_in[0];
    const float* y       = (const float*)d_in[1];
    const float* experts = (const float*)d_in[2];
    const float* gate_w  = (const float*)d_in[3];
    const float* gate_b  = (const float*)d_in[4];
    float* out = (float*)d_out;

    k_mean<<<BQ * CQ, 256>>>(y);
    k_gates<<<BQ, 256>>>(gate_w, gate_b);
    k_fold<<<OQ, 256>>>(experts);

    dim3 grid(32, 2, BQ);   // N-tiles x M-tiles x batch = 512 CTAs
    k_conv<<<grid, 256>>>(q, out);
}

// round 4
// speedup vs baseline: 6.9794x; 1.5380x over previous
#include <cuda_runtime.h>
#include <cuda_fp16.h>
#include <cstdint>

// Problem: B=8, C=256, H=W=64, O=256, K=3, E=3
// out[b,o,y,x] = sum_{c,t} w2[b,o,t,c] * q[b,c,y+kr-1,x+kc-1]
// w2[b,o,t,c] = fp16( sum_e gates[b,e]*(experts[e,o,c,t]+experts[e,o,c+C,t]) )
// Conv as fp16 mma.sync implicit GEMM. Per c-chunk (32 ch): cp.async all 9 tap
// A-tiles + stage im2col once, then 288 HMMAs/warp with no intervening barriers.

#define BQ 8
#define CQ 256
#define HQ 64
#define WQ 64
#define OQ 256

__device__ float  g_yctx[BQ * CQ];
__device__ float  g_gates[BQ * 3];
__device__ __half g_w2[(size_t)BQ * OQ * 2304];   // [b][o][t*256+c]

__device__ __forceinline__ uint32_t smem_u32(const void* p) {
    uint32_t a;
    asm("{ .reg .u64 t; cvta.to.shared.u64 t, %1; cvt.u32.u64 %0, t; }" : "=r"(a) : "l"(p));
    return a;
}

// ---------------------------------------------------------------------------
// Kernel 1: global average pool of y -> g_yctx
// ---------------------------------------------------------------------------
__global__ void k_mean(const float* __restrict__ y) {
    int bc = blockIdx.x;
    const float* p = y + (size_t)bc * (HQ * WQ);
    float s = 0.f;
    for (int i = threadIdx.x; i < HQ * WQ; i += 256) s += p[i];
    __shared__ float sm[256];
    sm[threadIdx.x] = s;
    __syncthreads();
    for (int st = 128; st > 0; st >>= 1) {
        if (threadIdx.x < st) sm[threadIdx.x] += sm[threadIdx.x + st];
        __syncthreads();
    }
    if (threadIdx.x == 0) g_yctx[bc] = sm[0] * (1.f / (HQ * WQ));
}

// ---------------------------------------------------------------------------
// Kernel 2: softmax gates
// ---------------------------------------------------------------------------
__global__ void k_gates(const float* __restrict__ gw, const float* __restrict__ gb) {
    int b = blockIdx.x;
    int c = threadIdx.x;
    float v = g_yctx[b * CQ + c];
    float p0 = v * (gw[c * 3 + 0] + gw[(c + CQ) * 3 + 0]);
    float p1 = v * (gw[c * 3 + 1] + gw[(c + CQ) * 3 + 1]);
    float p2 = v * (gw[c * 3 + 2] + gw[(c + CQ) * 3 + 2]);
    __shared__ float sm[3][256];
    sm[0][c] = p0; sm[1][c] = p1; sm[2][c] = p2;
    __syncthreads();
    for (int st = 128; st > 0; st >>= 1) {
        if (c < st) {
            sm[0][c] += sm[0][c + st];
            sm[1][c] += sm[1][c + st];
            sm[2][c] += sm[2][c + st];
        }
        __syncthreads();
    }
    if (c == 0) {
        float l0 = sm[0][0] + gb[0], l1 = sm[1][0] + gb[1], l2 = sm[2][0] + gb[2];
        float m = fmaxf(l0, fmaxf(l1, l2));
        float e0 = expf(l0 - m), e1 = expf(l1 - m), e2 = expf(l2 - m);
        float inv = 1.f / (e0 + e1 + e2);
        g_gates[b * 3 + 0] = e0 * inv;
        g_gates[b * 3 + 1] = e1 * inv;
        g_gates[b * 3 + 2] = e2 * inv;
    }
}

// ---------------------------------------------------------------------------
// Kernel 3: fold experts -> per-batch tap-major fp16 weights
// ---------------------------------------------------------------------------
__global__ void k_fold(const float* __restrict__ experts) {
    int o = blockIdx.x;
    int c = threadIdx.x;
    const size_t ES = (size_t)OQ * (2 * CQ) * 9;
    float f[3][9];
#pragma unroll
    for (int e = 0; e < 3; e++) {
        const float* p = experts + e * ES + (size_t)o * (2 * CQ * 9) + (size_t)c * 9;
#pragma unroll
        for (int t = 0; t < 9; t++) f[e][t] = p[t] + p[CQ * 9 + t];
    }
#pragma unroll
    for (int b = 0; b < BQ; b++) {
        float g0 = g_gates[b * 3 + 0];
        float g1 = g_gates[b * 3 + 1];
        float g2 = g_gates[b * 3 + 2];
        __half* wdst = g_w2 + ((size_t)b * OQ + o) * 2304;
#pragma unroll
        for (int t = 0; t < 9; t++)
            wdst[t * 256 + c] = __float2half_rn(g0 * f[0][t] + g1 * f[1][t] + g2 * f[2][t]);
    }
}

// ---------------------------------------------------------------------------
// Kernel 4: fp16 mma.sync implicit-GEMM conv.
// CTA: (b, o-half 128, 2 image rows = 128 px). 8 warps 2(M)x4(N), warp 64x32.
// Dynamic smem: A9 [9 t][128 o][32 ci] stride 80B (90KB, cp.async),
//               Bs [4 r][66 x][32 ci] stride 80B (20.6KB). One sync pair/chunk.
// ---------------------------------------------------------------------------
#define A_STRIDE 80
#define A9_BYTES (9 * 128 * A_STRIDE)      // 92160
#define S_STRIDE 80
#define BS_OFF   A9_BYTES
#define SM_TOTAL (A9_BYTES + 4 * 66 * S_STRIDE)   // 113280

__global__ __launch_bounds__(256, 2)
void k_conv(const float* __restrict__ q, float* __restrict__ out) {
    extern __shared__ __align__(16) unsigned char smc[];
    unsigned char* Bs = smc + BS_OFF;
    const uint32_t asBase = smem_u32(smc);

    int tid  = threadIdx.x;
    int lane = tid & 31;
    int warp = tid >> 5;
    int wm   = warp >> 2;      // 0..1  (64 o rows)
    int wn   = warp & 3;       // 0..3  (32 px cols)

    int nt = blockIdx.x;       // 0..31 : 2 image rows each
    int o0 = blockIdx.y * 128;
    int b  = blockIdx.z;
    int y0 = nt * 2;

    const float* qb = q + (size_t)b * CQ * HQ * WQ;
    const __half* wb = g_w2 + ((size_t)b * OQ + o0) * 2304;

    float acc[4][4][4];
#pragma unroll
    for (int i = 0; i < 4; i++)
#pragma unroll
        for (int j = 0; j < 4; j++)
#pragma unroll
            for (int k = 0; k < 4; k++) acc[i][j][k] = 0.f;

    int tg = lane & 3;
    int g8 = lane >> 2;

    for (int cc = 0; cc < 8; cc++) {
        int c0 = cc * 32;
        __syncthreads();   // previous chunk's MMA reads complete

        // ---- A9: cp.async all 9 taps, 18 x 16B per thread ----
        {
#pragma unroll
            for (int g = 0; g < 18; g++) {
                int idx = tid + g * 256;             // 0..4607
                int t   = idx >> 9;                  // /512
                int rem = idx & 511;
                int o   = rem >> 2;
                int qt  = rem & 3;                   // 16B quarter
                const __half* src = wb + (size_t)o * 2304 + t * 256 + c0 + qt * 8;
                uint32_t dst = asBase + (t * 128 + o) * A_STRIDE + qt * 16;
                asm volatile("cp.async.cg.shared.global [%0], [%1], 16;"
                             :: "r"(dst), "l"(src));
            }
            asm volatile("cp.async.commit_group;");
        }

        // ---- stage im2col chunk: [r][x][ci] fp16 pairs ----
        for (int pos = tid; pos < 264; pos += 256) {
            int r = pos / 66;
            int x = pos - r * 66;
            int gy = y0 - 1 + r;
            int gx = x - 1;
            bool ok = (unsigned)gy < (unsigned)HQ && (unsigned)gx < (unsigned)WQ;
            const float* src = qb + (size_t)c0 * (HQ * WQ) + gy * WQ + gx;
            uint32_t pk[16];
#pragma unroll
            for (int cp = 0; cp < 16; cp++) {
                float v0 = ok ? src[(2 * cp) * (HQ * WQ)] : 0.f;
                float v1 = ok ? src[(2 * cp + 1) * (HQ * WQ)] : 0.f;
                __half2 h = __floats2half2_rn(v0, v1);
                pk[cp] = *(uint32_t*)&h;
            }
            uint4* dst = (uint4*)(Bs + pos * S_STRIDE);
            dst[0] = make_uint4(pk[0], pk[1], pk[2], pk[3]);
            dst[1] = make_uint4(pk[4], pk[5], pk[6], pk[7]);
            dst[2] = make_uint4(pk[8], pk[9], pk[10], pk[11]);
            dst[3] = make_uint4(pk[12], pk[13], pk[14], pk[15]);
        }

        asm volatile("cp.async.wait_group 0;");
        __syncthreads();   // A9 + staging visible

        // ---- MMA phase: 9 taps, no barriers ----
#pragma unroll
        for (int t = 0; t < 9; t++) {
            int kr = t / 3, kc = t - kr * 3;
#pragma unroll
            for (int k16 = 0; k16 < 2; k16++) {
                uint32_t a[4][4];
#pragma unroll
                for (int fm = 0; fm < 4; fm++) {
                    int row = wm * 64 + fm * 16 + (lane & 15);
                    uint32_t addr = asBase + (t * 128 + row) * A_STRIDE
                                  + ((lane >> 4) << 4) + (k16 << 5);
                    asm volatile(
                        "ldmatrix.sync.aligned.m8n8.x4.shared.b16 {%0,%1,%2,%3}, [%4];"
                        : "=r"(a[fm][0]), "=r"(a[fm][1]), "=r"(a[fm][2]), "=r"(a[fm][3])
                        : "r"(addr));
                }
                uint32_t bf[4][2];
#pragma unroll
                for (int fn = 0; fn < 4; fn++) {
                    int n  = wn * 32 + fn * 8 + g8;
                    int py = n >> 6, px = n & 63;
                    const unsigned char* sp = Bs +
                        ((py + kr) * 66 + px + kc) * S_STRIDE + (k16 << 5) + (tg << 2);
                    bf[fn][0] = *(const uint32_t*)sp;
                    bf[fn][1] = *(const uint32_t*)(sp + 16);
                }
#pragma unroll
                for (int fm = 0; fm < 4; fm++)
#pragma unroll
                    for (int fn = 0; fn < 4; fn++) {
                        asm volatile(
                            "mma.sync.aligned.m16n8k16.row.col.f32.f16.f16.f32 "
                            "{%0,%1,%2,%3}, {%4,%5,%6,%7}, {%8,%9}, {%0,%1,%2,%3};"
                            : "+f"(acc[fm][fn][0]), "+f"(acc[fm][fn][1]),
                              "+f"(acc[fm][fn][2]), "+f"(acc[fm][fn][3])
                            : "r"(a[fm][0]), "r"(a[fm][1]), "r"(a[fm][2]), "r"(a[fm][3]),
                              "r"(bf[fn][0]), "r"(bf[fn][1]));
                    }
            }
        }
    }

    // ---- epilogue ----
#pragma unroll
    for (int fm = 0; fm < 4; fm++)
#pragma unroll
        for (int fn = 0; fn < 4; fn++) {
            int o  = o0 + wm * 64 + fm * 16 + g8;
            int n  = wn * 32 + fn * 8 + tg * 2;
            int py = n >> 6, px = n & 63;
            float* dst = out + (((size_t)(b * OQ + o)) * HQ + y0 + py) * WQ + px;
            *(float2*)dst = make_float2(acc[fm][fn][0], acc[fm][fn][1]);
            *(float2*)(dst + 8 * HQ * WQ) = make_float2(acc[fm][fn][2], acc[fm][fn][3]);
        }
}

// ---------------------------------------------------------------------------
extern "C" void kernel_launch(void* const* d_in, const int* in_sizes, int n_in,
                              void* d_out, int out_size) {
    const float* q       = (const float*)d_in[0];
    const float* y       = (const float*)d_in[1];
    const float* experts = (const float*)d_in[2];
    const float* gate_w  = (const float*)d_in[3];
    const float* gate_b  = (const float*)d_in[4];
    float* out = (float*)d_out;

    cudaFuncSetAttribute(k_conv, cudaFuncAttributeMaxDynamicSharedMemorySize, SM_TOTAL);

    k_mean<<<BQ * CQ, 256>>>(y);
    k_gates<<<BQ, 256>>>(gate_w, gate_b);
    k_fold<<<OQ, 256>>>(experts);

    dim3 grid(32, 2, BQ);   // 512 CTAs
    k_conv<<<grid, 256, SM_TOTAL>>>(q, out);
}